// round 8
// baseline (speedup 1.0000x reference)
#include <cuda_runtime.h>
#include <cuda_fp16.h>
#include <math.h>
#include <cstdint>

#define BATCH 2
#define NH    8
#define SEQ   4096
#define HD    64
#define WRD   512
#define MTOT  (BATCH*SEQ)     // 8192
#define NQKV  640             // 64 (K) + 64 (V) + 8*64 (Q)

// Q pre-scale: (1/sqrt(64)) * log2(e)  -> scores in log2 domain, exp2 for softmax
#define QSCALE 0.18033688011112042f

// ---------------- scratch (device globals; no allocation allowed) ----------------
__device__ __half g_xh[MTOT*WRD];            // x fp16 [8192,512]
__device__ __half g_WhT[NQKV*WRD];           // packed QKV weight, transposed [n][k] fp16
__device__ __half g_WpT[HD*WRD];             // Wp transposed [n][k] fp16
__device__ float  g_ball[NQKV];              // packed QKV bias fp32
__device__ __half g_Kh[BATCH*SEQ*HD];        // K  [b,t,d] fp16
__device__ __half g_Vth[BATCH*HD*SEQ];       // V^T [b,d,t] fp16
__device__ __half g_Qh[BATCH*NH*SEQ*HD];     // Q  [b,h,s,d] fp16 (pre-scaled)
__device__ __half g_Zch[BATCH*SEQ*NH*HD];    // concat heads [b,s,h*d] fp16

#define SW128(off) ((off) ^ (((off) >> 3) & 0x70))

__device__ __forceinline__ uint32_t smem_u32(const void* p) {
    uint32_t a;
    asm("{ .reg .u64 t; cvta.to.shared.u64 t, %1; cvt.u32.u64 %0, t; }" : "=r"(a) : "l"(p));
    return a;
}
__device__ __forceinline__ void mma16816(float c[4], const uint32_t a[4], const uint32_t b[2]) {
    asm volatile("mma.sync.aligned.m16n8k16.row.col.f32.f16.f16.f32 "
        "{%0,%1,%2,%3}, {%4,%5,%6,%7}, {%8,%9}, {%0,%1,%2,%3};"
        : "+f"(c[0]), "+f"(c[1]), "+f"(c[2]), "+f"(c[3])
        : "r"(a[0]), "r"(a[1]), "r"(a[2]), "r"(a[3]), "r"(b[0]), "r"(b[1]));
}
__device__ __forceinline__ void ldsm_x4(uint32_t d[4], uint32_t addr) {
    asm volatile("ldmatrix.sync.aligned.m8n8.x4.shared.b16 {%0,%1,%2,%3}, [%4];"
        : "=r"(d[0]), "=r"(d[1]), "=r"(d[2]), "=r"(d[3]) : "r"(addr));
}
__device__ __forceinline__ void cp16(uint32_t sdst, const void* gsrc) {
    asm volatile("cp.async.cg.shared.global [%0], [%1], 16;" :: "r"(sdst), "l"(gsrc));
}
#define CP_COMMIT() asm volatile("cp.async.commit_group;" ::: "memory")
#define CP_WAIT(n)  asm volatile("cp.async.wait_group %0;" :: "n"(n) : "memory")

// ---------------- kernel 1a: convert x to fp16 + pack bias ----------------
__global__ void prep_kernel(const float* __restrict__ x,
                            const float* __restrict__ bk,
                            const float* __restrict__ bv,
                            const float* __restrict__ bq)
{
    int idx = blockIdx.x * blockDim.x + threadIdx.x;

    if (idx < MTOT*WRD/8) {
        float4 a = *(const float4*)(x + idx*8);
        float4 b = *(const float4*)(x + idx*8 + 4);
        __half2 h[4] = { __floats2half2_rn(a.x, a.y), __floats2half2_rn(a.z, a.w),
                         __floats2half2_rn(b.x, b.y), __floats2half2_rn(b.z, b.w) };
        *(uint2*)(g_xh + idx*8)     = *(uint2*)&h[0];
        *(uint2*)(g_xh + idx*8 + 4) = *(uint2*)&h[2];
    }

    if (idx < NQKV) {
        float v;
        if (idx < 64)       v = bk[idx];
        else if (idx < 128) v = bv[idx-64];
        else                v = bq[idx-128];
        g_ball[idx] = v;
    }
}

// ---------------- kernel 1b: coalesced smem-tile weight transposes ----------------
__global__ void wtrans_kernel(const float* __restrict__ Wk, const float* __restrict__ Wv,
                              const float* __restrict__ Wq, const float* __restrict__ Wp)
{
    __shared__ float t[32][33];
    const int slab = blockIdx.z;
    const int k0 = blockIdx.x * 32, n0 = blockIdx.y * 32;
    const float* src;
    __half* dst;
    if (slab == 0)      src = Wk;
    else if (slab == 1) src = Wv;
    else if (slab < 10) src = Wq + (size_t)(slab-2)*WRD*HD;
    else                src = Wp;
    dst = (slab < 10) ? (g_WhT + (size_t)slab*64*WRD) : g_WpT;

    const int tx = threadIdx.x, ty = threadIdx.y;   // (32, 8)
    #pragma unroll
    for (int r = 0; r < 4; r++)
        t[ty + r*8][tx] = src[(size_t)(k0 + ty + r*8)*HD + n0 + tx];
    __syncthreads();
    #pragma unroll
    for (int r = 0; r < 4; r++) {
        int n = ty + r*8;
        dst[(size_t)(n0 + n)*WRD + k0 + tx] = __float2half_rn(t[tx][n]);
    }
}

// ---------------- kernel 2: QKV projection, cp.async double-buffered ----------------
// grid (64, 10), 256 thr (8 warps x 16 m-rows). Tile 128m x 64n, K-step 64.
__global__ __launch_bounds__(256) void qkv_mma_kernel()
{
    __shared__ __align__(128) char sA[2][128*128];   // 2 x 16KB
    __shared__ __align__(128) char sB[2][64*128];    // 2 x  8KB

    const int tid = threadIdx.x;
    const int wid = tid >> 5, lane = tid & 31;
    const int m0 = blockIdx.x * 128, n0 = blockIdx.y * 64;

    auto load_tiles = [&](int buf, int k0) {
        #pragma unroll
        for (int r = 0; r < 4; r++) {
            int i = tid + r*256;
            int row = i >> 3, c8 = (i & 7) * 8;
            cp16(smem_u32(sA[buf]) + SW128((uint32_t)(row*128 + c8*2)),
                 g_xh + (size_t)(m0 + row)*WRD + k0 + c8);
        }
        #pragma unroll
        for (int r = 0; r < 2; r++) {
            int i = tid + r*256;
            int row = i >> 3, c8 = (i & 7) * 8;
            cp16(smem_u32(sB[buf]) + SW128((uint32_t)(row*128 + c8*2)),
                 g_WhT + (size_t)(n0 + row)*WRD + k0 + c8);
        }
    };

    float acc[8][4] = {};

    load_tiles(0, 0); CP_COMMIT();

    for (int ki = 0; ki < 8; ki++) {
        if (ki < 7) { load_tiles((ki+1)&1, (ki+1)*64); CP_COMMIT(); CP_WAIT(1); }
        else CP_WAIT(0);
        __syncthreads();

        const uint32_t ab = smem_u32(sA[ki&1]), bb = smem_u32(sB[ki&1]);
        #pragma unroll
        for (int kk = 0; kk < 4; kk++) {
            uint32_t afr[4];
            {
                int row = wid*16 + (lane & 7) + ((lane >> 3) & 1) * 8;
                uint32_t col = (uint32_t)(kk*32 + ((lane >> 4) ? 16 : 0));
                ldsm_x4(afr, ab + SW128((uint32_t)row*128 + col));
            }
            uint32_t colb = (uint32_t)(kk*32 + ((lane & 8) ? 16 : 0));
            uint32_t rwb  = (uint32_t)(((lane & 16) ? 8 : 0) + (lane & 7));
            #pragma unroll
            for (int j2 = 0; j2 < 4; j2++) {
                uint32_t bfr[4];
                ldsm_x4(bfr, bb + SW128((j2*16 + rwb)*128 + colb));
                mma16816(acc[2*j2],   afr, bfr);
                mma16816(acc[2*j2+1], afr, bfr + 2);
            }
        }
        __syncthreads();
    }

    // ---- epilogue: bias + scatter to K / V^T / Q ----
    int r = wid*16 + (lane >> 2);
    #pragma unroll
    for (int j = 0; j < 8; j++) {
        #pragma unroll
        for (int e = 0; e < 2; e++) {
            int n = n0 + j*8 + (lane & 3)*2 + e;
            float bias = g_ball[n];
            #pragma unroll
            for (int rr = 0; rr < 2; rr++) {
                int m = m0 + r + rr*8;
                float v = acc[j][rr*2 + e] + bias;
                int b = m >> 12, s = m & 4095;
                if (n < 64) {
                    g_Kh[((size_t)b*SEQ + s)*HD + n] = __float2half_rn(v);
                } else if (n < 128) {
                    g_Vth[((size_t)b*HD + (n-64))*SEQ + s] = __float2half_rn(v);
                } else {
                    int nn = n - 128; int h = nn >> 6, d = nn & 63;
                    g_Qh[(((size_t)b*NH + h)*SEQ + s)*HD + d] = __float2half_rn(v * QSCALE);
                }
            }
        }
    }
}

// ---------------- kernel 3: mma.sync fp16 flash attention, fused S/exp/PV groups ----------------
// grid (SEQ/128, NH, BATCH), 128 threads = 4 warps x 32 q-rows.
// Per kt: 4 iterations of [S-MMA(16 cols) -> exp -> PV-MMA(k-step)] — short sc/pa live
// ranges (regs ~150) for 3 CTAs/SM, and fine-grain HMMA/MUFU interleave.
__global__ __launch_bounds__(128, 3) void attn_mma_kernel()
{
    __shared__ __align__(128) char sQ[128*128];     // 16KB
    __shared__ __align__(128) char sK[2][64*128];   // 2 x 8KB
    __shared__ __align__(128) char sV[2][64*128];   // 2 x 8KB

    const int tid  = threadIdx.x;
    const int wid  = tid >> 5, lane = tid & 31;
    const int b = blockIdx.z, hh = blockIdx.y, q0 = blockIdx.x * 128;

    const __half* Qp = g_Qh + ((size_t)(b*NH + hh)*SEQ + q0) * HD;
    const __half* Kp = g_Kh  + (size_t)b*SEQ*HD;
    const __half* Vp = g_Vth + (size_t)b*HD*SEQ;

    auto load_kv = [&](int buf, int kt) {
        #pragma unroll
        for (int r = 0; r < 4; r++) {
            int i = tid + r*128;
            int row = i >> 3, c8 = (i & 7) * 8;
            uint32_t off = SW128((uint32_t)(row*128 + c8*2));
            cp16(smem_u32(sK[buf]) + off, Kp + (size_t)(kt*64 + row)*HD + c8);
            cp16(smem_u32(sV[buf]) + off, Vp + (size_t)row*SEQ + kt*64 + c8);
        }
    };

    load_kv(0, 0); CP_COMMIT();

    // ---- Q tile -> smem -> register a-frags (2 a-tiles per warp) ----
    const uint32_t qb = smem_u32(sQ);
    #pragma unroll
    for (int r = 0; r < 8; r++) {
        int i = tid + r*128;
        int row = i >> 3, c8 = (i & 7) * 8;
        *(uint4*)(sQ + SW128((uint32_t)(row*128 + c8*2))) = *(const uint4*)(Qp + row*HD + c8);
    }
    __syncthreads();
    uint32_t qa[2][4][4];
    #pragma unroll
    for (int a = 0; a < 2; a++) {
        int row = wid*32 + a*16 + (lane & 7) + ((lane >> 3) & 1) * 8;
        #pragma unroll
        for (int kk = 0; kk < 4; kk++) {
            uint32_t col = (uint32_t)(kk*32 + ((lane >> 4) ? 16 : 0));
            ldsm_x4(qa[a][kk], qb + SW128((uint32_t)row*128 + col));
        }
    }

    float oc[2][8][4] = {};
    float ls[2][2] = {};
    const uint32_t colb = (uint32_t)((lane & 8) ? 16 : 0);
    const uint32_t rwb  = (uint32_t)(((lane & 16) ? 8 : 0) + (lane & 7));

    for (int kt = 0; kt < SEQ/64; kt++) {
        if (kt < SEQ/64 - 1) { load_kv((kt+1)&1, kt+1); CP_COMMIT(); CP_WAIT(1); }
        else CP_WAIT(0);
        __syncthreads();

        const uint32_t kb_ = smem_u32(sK[kt&1]), vb_ = smem_u32(sV[kt&1]);

        __half2 kls[2][2];
        #pragma unroll
        for (int a = 0; a < 2; a++) { kls[a][0] = __float2half2_rn(0.f); kls[a][1] = __float2half2_rn(0.f); }

        // ---- fused groups: S (n-tiles 2j2,2j2+1) -> exp -> PV (k-step j2) ----
        #pragma unroll
        for (int j2 = 0; j2 < 4; j2++) {
            // S-MMA for this 16-col group
            float sc[2][2][4] = {};
            #pragma unroll
            for (int kk = 0; kk < 4; kk++) {
                uint32_t bfr[4];
                ldsm_x4(bfr, kb_ + SW128((j2*16 + rwb)*128 + (uint32_t)(kk*32) + colb));
                #pragma unroll
                for (int a = 0; a < 2; a++) {
                    mma16816(sc[a][0], qa[a][kk], bfr);
                    mma16816(sc[a][1], qa[a][kk], bfr + 2);
                }
            }

            // exp2 -> P a-frags for PV k-step j2
            uint32_t pa[2][4];
            #pragma unroll
            for (int a = 0; a < 2; a++) {
                __half2 p0 = h2exp2(__floats2half2_rn(sc[a][0][0], sc[a][0][1]));
                __half2 p1 = h2exp2(__floats2half2_rn(sc[a][0][2], sc[a][0][3]));
                __half2 p2 = h2exp2(__floats2half2_rn(sc[a][1][0], sc[a][1][1]));
                __half2 p3 = h2exp2(__floats2half2_rn(sc[a][1][2], sc[a][1][3]));
                kls[a][0] = __hadd2(kls[a][0], __hadd2(p0, p2));
                kls[a][1] = __hadd2(kls[a][1], __hadd2(p1, p3));
                pa[a][0] = *(uint32_t*)&p0;
                pa[a][1] = *(uint32_t*)&p1;
                pa[a][2] = *(uint32_t*)&p2;
                pa[a][3] = *(uint32_t*)&p3;
            }

            // PV-MMA (k-step j2) over all 8 d-tiles
            #pragma unroll
            for (int jv = 0; jv < 4; jv++) {
                uint32_t bfr[4];
                ldsm_x4(bfr, vb_ + SW128((jv*16 + rwb)*128 + (uint32_t)(j2*32) + colb));
                #pragma unroll
                for (int a = 0; a < 2; a++) {
                    mma16816(oc[a][2*jv],   pa[a], bfr);
                    mma16816(oc[a][2*jv+1], pa[a], bfr + 2);
                }
            }
        }

        #pragma unroll
        for (int a = 0; a < 2; a++) {
            float2 fa = __half22float2(kls[a][0]);
            float2 fb = __half22float2(kls[a][1]);
            ls[a][0] += fa.x + fa.y;
            ls[a][1] += fb.x + fb.y;
        }
        __syncthreads();
    }

    // ---- reduce row sums across the 4 lanes sharing each row ----
    #pragma unroll
    for (int a = 0; a < 2; a++) {
        #pragma unroll
        for (int e = 0; e < 2; e++) {
            ls[a][e] += __shfl_xor_sync(0xffffffffu, ls[a][e], 1);
            ls[a][e] += __shfl_xor_sync(0xffffffffu, ls[a][e], 2);
        }
    }

    // ---- write O (fp16 concat-head layout) ----
    int c0 = (lane & 3) * 2;
    #pragma unroll
    for (int a = 0; a < 2; a++) {
        float inv0 = 1.0f / ls[a][0], inv1 = 1.0f / ls[a][1];
        int r = wid*32 + a*16 + (lane >> 2);
        __half* Z0 = g_Zch + ((size_t)(b*SEQ) + q0 + r    )*(NH*HD) + hh*HD;
        __half* Z1 = g_Zch + ((size_t)(b*SEQ) + q0 + r + 8)*(NH*HD) + hh*HD;
        #pragma unroll
        for (int j = 0; j < 8; j++) {
            int d = j*8 + c0;
            *(__half2*)(Z0 + d) = __floats2half2_rn(oc[a][j][0]*inv0, oc[a][j][1]*inv0);
            *(__half2*)(Z1 + d) = __floats2half2_rn(oc[a][j][2]*inv1, oc[a][j][3]*inv1);
        }
    }
}

// ---------------- kernel 4: output projection, cp.async double-buffered ----------------
// grid (128), 128 thr (4 warps x 16 m-rows). Tile 64m x 64n, K-step 64.
__global__ __launch_bounds__(128) void oproj_mma_kernel(const float* __restrict__ bp,
                                                        float* __restrict__ out)
{
    __shared__ __align__(128) char sA[2][64*128];    // 2 x 8KB
    __shared__ __align__(128) char sB[2][64*128];    // 2 x 8KB

    const int tid = threadIdx.x;
    const int wid = tid >> 5, lane = tid & 31;
    const int m0 = blockIdx.x * 64;

    auto load_tiles = [&](int buf, int k0) {
        #pragma unroll
        for (int r = 0; r < 4; r++) {
            int i = tid + r*128;
            int row = i >> 3, c8 = (i & 7) * 8;
            uint32_t off = SW128((uint32_t)(row*128 + c8*2));
            cp16(smem_u32(sA[buf]) + off, g_Zch + (size_t)(m0 + row)*WRD + k0 + c8);
            cp16(smem_u32(sB[buf]) + off, g_WpT + (size_t)row*WRD + k0 + c8);
        }
    };

    float acc[8][4] = {};

    load_tiles(0, 0); CP_COMMIT();

    for (int ki = 0; ki < 8; ki++) {
        if (ki < 7) { load_tiles((ki+1)&1, (ki+1)*64); CP_COMMIT(); CP_WAIT(1); }
        else CP_WAIT(0);
        __syncthreads();

        const uint32_t ab = smem_u32(sA[ki&1]), bb = smem_u32(sB[ki&1]);
        #pragma unroll
        for (int kk = 0; kk < 4; kk++) {
            uint32_t afr[4];
            {
                int row = wid*16 + (lane & 7) + ((lane >> 3) & 1) * 8;
                uint32_t col = (uint32_t)(kk*32 + ((lane >> 4) ? 16 : 0));
                ldsm_x4(afr, ab + SW128((uint32_t)row*128 + col));
            }
            uint32_t colb = (uint32_t)(kk*32 + ((lane & 8) ? 16 : 0));
            uint32_t rwb  = (uint32_t)(((lane & 16) ? 8 : 0) + (lane & 7));
            #pragma unroll
            for (int j2 = 0; j2 < 4; j2++) {
                uint32_t bfr[4];
                ldsm_x4(bfr, bb + SW128((j2*16 + rwb)*128 + colb));
                mma16816(acc[2*j2],   afr, bfr);
                mma16816(acc[2*j2+1], afr, bfr + 2);
            }
        }
        __syncthreads();
    }

    int r  = wid*16 + (lane >> 2);
    int c0 = (lane & 3) * 2;
    float* O0 = out + (size_t)(m0 + r    )*HD;
    float* O1 = out + (size_t)(m0 + r + 8)*HD;
    #pragma unroll
    for (int j = 0; j < 8; j++) {
        int n = j*8 + c0;
        float b0 = bp[n], b1 = bp[n+1];
        *(float2*)(O0 + n) = make_float2(acc[j][0] + b0, acc[j][1] + b1);
        *(float2*)(O1 + n) = make_float2(acc[j][2] + b0, acc[j][3] + b1);
    }
}

// ---------------- launch ----------------
extern "C" void kernel_launch(void* const* d_in, const int* in_sizes, int n_in,
                              void* d_out, int out_size)
{
    const float* x  = (const float*)d_in[0];
    const float* Wq = (const float*)d_in[1];
    const float* bq = (const float*)d_in[2];
    const float* Wk = (const float*)d_in[3];
    const float* bk = (const float*)d_in[4];
    const float* Wv = (const float*)d_in[5];
    const float* bv = (const float*)d_in[6];
    const float* Wp = (const float*)d_in[7];
    const float* bp = (const float*)d_in[8];
    float* out = (float*)d_out;

    prep_kernel<<<(MTOT*WRD/8 + 255)/256, 256>>>(x, bk, bv, bq);
    wtrans_kernel<<<dim3(16, 2, 11), dim3(32, 8)>>>(Wk, Wv, Wq, Wp);

    qkv_mma_kernel<<<dim3(MTOT/128, NQKV/64), 256>>>();

    attn_mma_kernel<<<dim3(SEQ/128, NH, BATCH), 128>>>();

    oproj_mma_kernel<<<dim3(MTOT/64), 128>>>(bp, out);
}

// round 9
// speedup vs baseline: 1.0727x; 1.0727x over previous
#include <cuda_runtime.h>
#include <cuda_fp16.h>
#include <math.h>
#include <cstdint>

#define BATCH 2
#define NH    8
#define SEQ   4096
#define HD    64
#define WRD   512
#define MTOT  (BATCH*SEQ)     // 8192
#define NQKV  640             // 64 (K) + 64 (V) + 8*64 (Q)

// Q pre-scale: (1/sqrt(64)) * log2(e)  -> scores in log2 domain, exp2 for softmax
#define QSCALE 0.18033688011112042f

// ---------------- scratch (device globals; no allocation allowed) ----------------
__device__ __half g_xh[MTOT*WRD];            // x fp16 [8192,512]
__device__ __half g_WhT[NQKV*WRD];           // packed QKV weight, transposed [n][k] fp16
__device__ __half g_WpT[HD*WRD];             // Wp transposed [n][k] fp16
__device__ float  g_ball[NQKV];              // packed QKV bias fp32
__device__ __half g_Kh[BATCH*SEQ*HD];        // K  [b,t,d] fp16
__device__ __half g_Vth[BATCH*HD*SEQ];       // V^T [b,d,t] fp16
__device__ __half g_Qh[BATCH*NH*SEQ*HD];     // Q  [b,h,s,d] fp16 (pre-scaled)
__device__ __half g_Zch[BATCH*SEQ*NH*HD];    // concat heads [b,s,h*d] fp16

#define SW128(off) ((off) ^ (((off) >> 3) & 0x70))

__device__ __forceinline__ uint32_t smem_u32(const void* p) {
    uint32_t a;
    asm("{ .reg .u64 t; cvta.to.shared.u64 t, %1; cvt.u32.u64 %0, t; }" : "=r"(a) : "l"(p));
    return a;
}
__device__ __forceinline__ void mma16816(float c[4], const uint32_t a[4], const uint32_t b[2]) {
    asm volatile("mma.sync.aligned.m16n8k16.row.col.f32.f16.f16.f32 "
        "{%0,%1,%2,%3}, {%4,%5,%6,%7}, {%8,%9}, {%0,%1,%2,%3};"
        : "+f"(c[0]), "+f"(c[1]), "+f"(c[2]), "+f"(c[3])
        : "r"(a[0]), "r"(a[1]), "r"(a[2]), "r"(a[3]), "r"(b[0]), "r"(b[1]));
}
__device__ __forceinline__ void ldsm_x4(uint32_t d[4], uint32_t addr) {
    asm volatile("ldmatrix.sync.aligned.m8n8.x4.shared.b16 {%0,%1,%2,%3}, [%4];"
        : "=r"(d[0]), "=r"(d[1]), "=r"(d[2]), "=r"(d[3]) : "r"(addr));
}
__device__ __forceinline__ void cp16(uint32_t sdst, const void* gsrc) {
    asm volatile("cp.async.cg.shared.global [%0], [%1], 16;" :: "r"(sdst), "l"(gsrc));
}
#define CP_COMMIT() asm volatile("cp.async.commit_group;" ::: "memory")
#define CP_WAIT(n)  asm volatile("cp.async.wait_group %0;" :: "n"(n) : "memory")

// ---------------- kernel 1a: convert x to fp16 + pack bias ----------------
__global__ void prep_kernel(const float* __restrict__ x,
                            const float* __restrict__ bk,
                            const float* __restrict__ bv,
                            const float* __restrict__ bq)
{
    int idx = blockIdx.x * blockDim.x + threadIdx.x;

    if (idx < MTOT*WRD/8) {
        float4 a = *(const float4*)(x + idx*8);
        float4 b = *(const float4*)(x + idx*8 + 4);
        __half2 h[4] = { __floats2half2_rn(a.x, a.y), __floats2half2_rn(a.z, a.w),
                         __floats2half2_rn(b.x, b.y), __floats2half2_rn(b.z, b.w) };
        *(uint2*)(g_xh + idx*8)     = *(uint2*)&h[0];
        *(uint2*)(g_xh + idx*8 + 4) = *(uint2*)&h[2];
    }

    if (idx < NQKV) {
        float v;
        if (idx < 64)       v = bk[idx];
        else if (idx < 128) v = bv[idx-64];
        else                v = bq[idx-128];
        g_ball[idx] = v;
    }
}

// ---------------- kernel 1b: coalesced smem-tile weight transposes ----------------
__global__ void wtrans_kernel(const float* __restrict__ Wk, const float* __restrict__ Wv,
                              const float* __restrict__ Wq, const float* __restrict__ Wp)
{
    __shared__ float t[32][33];
    const int slab = blockIdx.z;
    const int k0 = blockIdx.x * 32, n0 = blockIdx.y * 32;
    const float* src;
    __half* dst;
    if (slab == 0)      src = Wk;
    else if (slab == 1) src = Wv;
    else if (slab < 10) src = Wq + (size_t)(slab-2)*WRD*HD;
    else                src = Wp;
    dst = (slab < 10) ? (g_WhT + (size_t)slab*64*WRD) : g_WpT;

    const int tx = threadIdx.x, ty = threadIdx.y;   // (32, 8)
    #pragma unroll
    for (int r = 0; r < 4; r++)
        t[ty + r*8][tx] = src[(size_t)(k0 + ty + r*8)*HD + n0 + tx];
    __syncthreads();
    #pragma unroll
    for (int r = 0; r < 4; r++) {
        int n = ty + r*8;
        dst[(size_t)(n0 + n)*WRD + k0 + tx] = __float2half_rn(t[tx][n]);
    }
}

// ---------------- kernel 2: QKV projection, cp.async double-buffered ----------------
// grid (64, 10), 256 thr (8 warps x 16 m-rows). Tile 128m x 64n, K-step 64.
__global__ __launch_bounds__(256) void qkv_mma_kernel()
{
    __shared__ __align__(128) char sA[2][128*128];   // 2 x 16KB
    __shared__ __align__(128) char sB[2][64*128];    // 2 x  8KB

    const int tid = threadIdx.x;
    const int wid = tid >> 5, lane = tid & 31;
    const int m0 = blockIdx.x * 128, n0 = blockIdx.y * 64;

    auto load_tiles = [&](int buf, int k0) {
        #pragma unroll
        for (int r = 0; r < 4; r++) {
            int i = tid + r*256;
            int row = i >> 3, c8 = (i & 7) * 8;
            cp16(smem_u32(sA[buf]) + SW128((uint32_t)(row*128 + c8*2)),
                 g_xh + (size_t)(m0 + row)*WRD + k0 + c8);
        }
        #pragma unroll
        for (int r = 0; r < 2; r++) {
            int i = tid + r*256;
            int row = i >> 3, c8 = (i & 7) * 8;
            cp16(smem_u32(sB[buf]) + SW128((uint32_t)(row*128 + c8*2)),
                 g_WhT + (size_t)(n0 + row)*WRD + k0 + c8);
        }
    };

    float acc[8][4] = {};

    load_tiles(0, 0); CP_COMMIT();

    for (int ki = 0; ki < 8; ki++) {
        if (ki < 7) { load_tiles((ki+1)&1, (ki+1)*64); CP_COMMIT(); CP_WAIT(1); }
        else CP_WAIT(0);
        __syncthreads();

        const uint32_t ab = smem_u32(sA[ki&1]), bb = smem_u32(sB[ki&1]);
        #pragma unroll
        for (int kk = 0; kk < 4; kk++) {
            uint32_t afr[4];
            {
                int row = wid*16 + (lane & 7) + ((lane >> 3) & 1) * 8;
                uint32_t col = (uint32_t)(kk*32 + ((lane >> 4) ? 16 : 0));
                ldsm_x4(afr, ab + SW128((uint32_t)row*128 + col));
            }
            uint32_t colb = (uint32_t)(kk*32 + ((lane & 8) ? 16 : 0));
            uint32_t rwb  = (uint32_t)(((lane & 16) ? 8 : 0) + (lane & 7));
            #pragma unroll
            for (int j2 = 0; j2 < 4; j2++) {
                uint32_t bfr[4];
                ldsm_x4(bfr, bb + SW128((j2*16 + rwb)*128 + colb));
                mma16816(acc[2*j2],   afr, bfr);
                mma16816(acc[2*j2+1], afr, bfr + 2);
            }
        }
        __syncthreads();
    }

    // ---- epilogue: bias + scatter to K / V^T / Q ----
    int r = wid*16 + (lane >> 2);
    #pragma unroll
    for (int j = 0; j < 8; j++) {
        #pragma unroll
        for (int e = 0; e < 2; e++) {
            int n = n0 + j*8 + (lane & 3)*2 + e;
            float bias = g_ball[n];
            #pragma unroll
            for (int rr = 0; rr < 2; rr++) {
                int m = m0 + r + rr*8;
                float v = acc[j][rr*2 + e] + bias;
                int b = m >> 12, s = m & 4095;
                if (n < 64) {
                    g_Kh[((size_t)b*SEQ + s)*HD + n] = __float2half_rn(v);
                } else if (n < 128) {
                    g_Vth[((size_t)b*HD + (n-64))*SEQ + s] = __float2half_rn(v);
                } else {
                    int nn = n - 128; int h = nn >> 6, d = nn & 63;
                    g_Qh[(((size_t)b*NH + h)*SEQ + s)*HD + d] = __float2half_rn(v * QSCALE);
                }
            }
        }
    }
}

// ---------------- kernel 3: mma.sync fp16 flash attention (monolithic phases) ----------------
// grid (SEQ/128, NH, BATCH), 128 threads = 4 warps x 32 q-rows.
// lsum computed on the tensor pipe via P @ ones (constant b-frag), removing the
// hadd2/fold chains from the exp phase and the end shfl reduction.
__global__ __launch_bounds__(128, 2) void attn_mma_kernel()
{
    __shared__ __align__(128) char sQ[128*128];     // 16KB
    __shared__ __align__(128) char sK[2][64*128];   // 2 x 8KB
    __shared__ __align__(128) char sV[2][64*128];   // 2 x 8KB

    const int tid  = threadIdx.x;
    const int wid  = tid >> 5, lane = tid & 31;
    const int b = blockIdx.z, hh = blockIdx.y, q0 = blockIdx.x * 128;

    const __half* Qp = g_Qh + ((size_t)(b*NH + hh)*SEQ + q0) * HD;
    const __half* Kp = g_Kh  + (size_t)b*SEQ*HD;
    const __half* Vp = g_Vth + (size_t)b*HD*SEQ;

    auto load_kv = [&](int buf, int kt) {
        #pragma unroll
        for (int r = 0; r < 4; r++) {
            int i = tid + r*128;
            int row = i >> 3, c8 = (i & 7) * 8;
            uint32_t off = SW128((uint32_t)(row*128 + c8*2));
            cp16(smem_u32(sK[buf]) + off, Kp + (size_t)(kt*64 + row)*HD + c8);
            cp16(smem_u32(sV[buf]) + off, Vp + (size_t)row*SEQ + kt*64 + c8);
        }
    };

    load_kv(0, 0); CP_COMMIT();

    // ---- Q tile -> smem -> register a-frags (2 a-tiles per warp) ----
    const uint32_t qb = smem_u32(sQ);
    #pragma unroll
    for (int r = 0; r < 8; r++) {
        int i = tid + r*128;
        int row = i >> 3, c8 = (i & 7) * 8;
        *(uint4*)(sQ + SW128((uint32_t)(row*128 + c8*2))) = *(const uint4*)(Qp + row*HD + c8);
    }
    __syncthreads();
    uint32_t qa[2][4][4];
    #pragma unroll
    for (int a = 0; a < 2; a++) {
        int row = wid*32 + a*16 + (lane & 7) + ((lane >> 3) & 1) * 8;
        #pragma unroll
        for (int kk = 0; kk < 4; kk++) {
            uint32_t col = (uint32_t)(kk*32 + ((lane >> 4) ? 16 : 0));
            ldsm_x4(qa[a][kk], qb + SW128((uint32_t)row*128 + col));
        }
    }

    float oc[2][8][4] = {};
    float lsacc[2][4] = {};                     // tensor-pipe lsum accumulators (P @ ones)
    const uint32_t ones_frag[2] = { 0x3C003C00u, 0x3C003C00u };  // fp16 1.0 x4
    const uint32_t colb = (uint32_t)((lane & 8) ? 16 : 0);
    const uint32_t rwb  = (uint32_t)(((lane & 16) ? 8 : 0) + (lane & 7));

    for (int kt = 0; kt < SEQ/64; kt++) {
        if (kt < SEQ/64 - 1) { load_kv((kt+1)&1, kt+1); CP_COMMIT(); CP_WAIT(1); }
        else CP_WAIT(0);
        __syncthreads();

        const uint32_t kb_ = smem_u32(sK[kt&1]), vb_ = smem_u32(sV[kt&1]);

        // ---- S = Q @ K^T : each K b-frag feeds 4 MMAs ----
        float sc[2][8][4] = {};
        #pragma unroll
        for (int kk = 0; kk < 4; kk++) {
            uint32_t cc = (uint32_t)(kk*32) + colb;
            #pragma unroll
            for (int j2 = 0; j2 < 4; j2++) {
                uint32_t bfr[4];
                ldsm_x4(bfr, kb_ + SW128((j2*16 + rwb)*128 + cc));
                #pragma unroll
                for (int a = 0; a < 2; a++) {
                    mma16816(sc[a][2*j2],   qa[a][kk], bfr);
                    mma16816(sc[a][2*j2+1], qa[a][kk], bfr + 2);
                }
            }
        }

        // ---- exp2 in f16x2: pack + MUFU only (no sum chains) ----
        uint32_t pa[2][4][4];
        #pragma unroll
        for (int a = 0; a < 2; a++) {
            #pragma unroll
            for (int j = 0; j < 8; j++) {
                __half2 p01 = h2exp2(__floats2half2_rn(sc[a][j][0], sc[a][j][1]));
                __half2 p23 = h2exp2(__floats2half2_rn(sc[a][j][2], sc[a][j][3]));
                pa[a][j >> 1][(j & 1)*2 + 0] = *(uint32_t*)&p01;
                pa[a][j >> 1][(j & 1)*2 + 1] = *(uint32_t*)&p23;
            }
        }

        // ---- O += P @ V^T, lsum += P @ ones : each V b-frag feeds 4 MMAs ----
        #pragma unroll
        for (int tt = 0; tt < 4; tt++) {
            uint32_t cc = (uint32_t)(tt*32) + colb;
            #pragma unroll
            for (int jv = 0; jv < 4; jv++) {
                uint32_t bfr[4];
                ldsm_x4(bfr, vb_ + SW128((jv*16 + rwb)*128 + cc));
                #pragma unroll
                for (int a = 0; a < 2; a++) {
                    mma16816(oc[a][2*jv],   pa[a][tt], bfr);
                    mma16816(oc[a][2*jv+1], pa[a][tt], bfr + 2);
                }
            }
            #pragma unroll
            for (int a = 0; a < 2; a++)
                mma16816(lsacc[a], pa[a][tt], ones_frag);
        }
        __syncthreads();
    }

    // ---- write O (fp16 concat-head layout); lsum already complete per lane ----
    int c0 = (lane & 3) * 2;
    #pragma unroll
    for (int a = 0; a < 2; a++) {
        float inv0 = 1.0f / lsacc[a][0], inv1 = 1.0f / lsacc[a][2];
        int r = wid*32 + a*16 + (lane >> 2);
        __half* Z0 = g_Zch + ((size_t)(b*SEQ) + q0 + r    )*(NH*HD) + hh*HD;
        __half* Z1 = g_Zch + ((size_t)(b*SEQ) + q0 + r + 8)*(NH*HD) + hh*HD;
        #pragma unroll
        for (int j = 0; j < 8; j++) {
            int d = j*8 + c0;
            *(__half2*)(Z0 + d) = __floats2half2_rn(oc[a][j][0]*inv0, oc[a][j][1]*inv0);
            *(__half2*)(Z1 + d) = __floats2half2_rn(oc[a][j][2]*inv1, oc[a][j][3]*inv1);
        }
    }
}

// ---------------- kernel 4: output projection, cp.async double-buffered ----------------
// grid (128), 128 thr (4 warps x 16 m-rows). Tile 64m x 64n, K-step 64.
__global__ __launch_bounds__(128) void oproj_mma_kernel(const float* __restrict__ bp,
                                                        float* __restrict__ out)
{
    __shared__ __align__(128) char sA[2][64*128];    // 2 x 8KB
    __shared__ __align__(128) char sB[2][64*128];    // 2 x 8KB

    const int tid = threadIdx.x;
    const int wid = tid >> 5, lane = tid & 31;
    const int m0 = blockIdx.x * 64;

    auto load_tiles = [&](int buf, int k0) {
        #pragma unroll
        for (int r = 0; r < 4; r++) {
            int i = tid + r*128;
            int row = i >> 3, c8 = (i & 7) * 8;
            uint32_t off = SW128((uint32_t)(row*128 + c8*2));
            cp16(smem_u32(sA[buf]) + off, g_Zch + (size_t)(m0 + row)*WRD + k0 + c8);
            cp16(smem_u32(sB[buf]) + off, g_WpT + (size_t)row*WRD + k0 + c8);
        }
    };

    float acc[8][4] = {};

    load_tiles(0, 0); CP_COMMIT();

    for (int ki = 0; ki < 8; ki++) {
        if (ki < 7) { load_tiles((ki+1)&1, (ki+1)*64); CP_COMMIT(); CP_WAIT(1); }
        else CP_WAIT(0);
        __syncthreads();

        const uint32_t ab = smem_u32(sA[ki&1]), bb = smem_u32(sB[ki&1]);
        #pragma unroll
        for (int kk = 0; kk < 4; kk++) {
            uint32_t afr[4];
            {
                int row = wid*16 + (lane & 7) + ((lane >> 3) & 1) * 8;
                uint32_t col = (uint32_t)(kk*32 + ((lane >> 4) ? 16 : 0));
                ldsm_x4(afr, ab + SW128((uint32_t)row*128 + col));
            }
            uint32_t colb = (uint32_t)(kk*32 + ((lane & 8) ? 16 : 0));
            uint32_t rwb  = (uint32_t)(((lane & 16) ? 8 : 0) + (lane & 7));
            #pragma unroll
            for (int j2 = 0; j2 < 4; j2++) {
                uint32_t bfr[4];
                ldsm_x4(bfr, bb + SW128((j2*16 + rwb)*128 + colb));
                mma16816(acc[2*j2],   afr, bfr);
                mma16816(acc[2*j2+1], afr, bfr + 2);
            }
        }
        __syncthreads();
    }

    int r  = wid*16 + (lane >> 2);
    int c0 = (lane & 3) * 2;
    float* O0 = out + (size_t)(m0 + r    )*HD;
    float* O1 = out + (size_t)(m0 + r + 8)*HD;
    #pragma unroll
    for (int j = 0; j < 8; j++) {
        int n = j*8 + c0;
        float b0 = bp[n], b1 = bp[n+1];
        *(float2*)(O0 + n) = make_float2(acc[j][0] + b0, acc[j][1] + b1);
        *(float2*)(O1 + n) = make_float2(acc[j][2] + b0, acc[j][3] + b1);
    }
}

// ---------------- launch ----------------
extern "C" void kernel_launch(void* const* d_in, const int* in_sizes, int n_in,
                              void* d_out, int out_size)
{
    const float* x  = (const float*)d_in[0];
    const float* Wq = (const float*)d_in[1];
    const float* bq = (const float*)d_in[2];
    const float* Wk = (const float*)d_in[3];
    const float* bk = (const float*)d_in[4];
    const float* Wv = (const float*)d_in[5];
    const float* bv = (const float*)d_in[6];
    const float* Wp = (const float*)d_in[7];
    const float* bp = (const float*)d_in[8];
    float* out = (float*)d_out;

    prep_kernel<<<(MTOT*WRD/8 + 255)/256, 256>>>(x, bk, bv, bq);
    wtrans_kernel<<<dim3(16, 2, 11), dim3(32, 8)>>>(Wk, Wv, Wq, Wp);

    qkv_mma_kernel<<<dim3(MTOT/128, NQKV/64), 256>>>();

    attn_mma_kernel<<<dim3(SEQ/128, NH, BATCH), 128>>>();

    oproj_mma_kernel<<<dim3(MTOT/64), 128>>>(bp, out);
}

// round 10
// speedup vs baseline: 1.0779x; 1.0048x over previous
#include <cuda_runtime.h>
#include <cuda_fp16.h>
#include <math.h>
#include <cstdint>

#define BATCH 2
#define NH    8
#define SEQ   4096
#define HD    64
#define WRD   512
#define MTOT  (BATCH*SEQ)     // 8192
#define NQKV  640             // 64 (K) + 64 (V) + 8*64 (Q)

// Q pre-scale: (1/sqrt(64)) * log2(e)  -> scores in log2 domain, exp2 for softmax
#define QSCALE 0.18033688011112042f

// ---------------- scratch (device globals; no allocation allowed) ----------------
__device__ __half g_xh[MTOT*WRD];            // x fp16 [8192,512]
__device__ __half g_WhT[NQKV*WRD];           // packed QKV weight, transposed [n][k] fp16
__device__ __half g_WpT[HD*WRD];             // Wp transposed [n][k] fp16
__device__ float  g_ball[NQKV];              // packed QKV bias fp32
__device__ __half g_Kh[BATCH*SEQ*HD];        // K  [b,t,d] fp16
__device__ __half g_Vth[BATCH*HD*SEQ];       // V^T [b,d,t] fp16
__device__ __half g_Qh[BATCH*NH*SEQ*HD];     // Q  [b,h,s,d] fp16 (pre-scaled)
__device__ __half g_Zch[BATCH*SEQ*NH*HD];    // concat heads [b,s,h*d] fp16

#define SW128(off) ((off) ^ (((off) >> 3) & 0x70))

__device__ __forceinline__ uint32_t smem_u32(const void* p) {
    uint32_t a;
    asm("{ .reg .u64 t; cvta.to.shared.u64 t, %1; cvt.u32.u64 %0, t; }" : "=r"(a) : "l"(p));
    return a;
}
__device__ __forceinline__ void mma16816(float c[4], const uint32_t a[4], const uint32_t b[2]) {
    asm volatile("mma.sync.aligned.m16n8k16.row.col.f32.f16.f16.f32 "
        "{%0,%1,%2,%3}, {%4,%5,%6,%7}, {%8,%9}, {%0,%1,%2,%3};"
        : "+f"(c[0]), "+f"(c[1]), "+f"(c[2]), "+f"(c[3])
        : "r"(a[0]), "r"(a[1]), "r"(a[2]), "r"(a[3]), "r"(b[0]), "r"(b[1]));
}
// fp16-accumulated MMA: c-frag (2 regs) doubles as the P a-frag after in-place exp
__device__ __forceinline__ void mma16816_f16(uint32_t c[2], const uint32_t a[4], const uint32_t b[2]) {
    asm volatile("mma.sync.aligned.m16n8k16.row.col.f16.f16.f16.f16 "
        "{%0,%1}, {%2,%3,%4,%5}, {%6,%7}, {%0,%1};"
        : "+r"(c[0]), "+r"(c[1])
        : "r"(a[0]), "r"(a[1]), "r"(a[2]), "r"(a[3]), "r"(b[0]), "r"(b[1]));
}
__device__ __forceinline__ void ldsm_x4(uint32_t d[4], uint32_t addr) {
    asm volatile("ldmatrix.sync.aligned.m8n8.x4.shared.b16 {%0,%1,%2,%3}, [%4];"
        : "=r"(d[0]), "=r"(d[1]), "=r"(d[2]), "=r"(d[3]) : "r"(addr));
}
__device__ __forceinline__ void cp16(uint32_t sdst, const void* gsrc) {
    asm volatile("cp.async.cg.shared.global [%0], [%1], 16;" :: "r"(sdst), "l"(gsrc));
}
#define CP_COMMIT() asm volatile("cp.async.commit_group;" ::: "memory")
#define CP_WAIT(n)  asm volatile("cp.async.wait_group %0;" :: "n"(n) : "memory")

// ---------------- kernel 1a: convert x to fp16 + pack bias ----------------
__global__ void prep_kernel(const float* __restrict__ x,
                            const float* __restrict__ bk,
                            const float* __restrict__ bv,
                            const float* __restrict__ bq)
{
    int idx = blockIdx.x * blockDim.x + threadIdx.x;

    if (idx < MTOT*WRD/8) {
        float4 a = *(const float4*)(x + idx*8);
        float4 b = *(const float4*)(x + idx*8 + 4);
        __half2 h[4] = { __floats2half2_rn(a.x, a.y), __floats2half2_rn(a.z, a.w),
                         __floats2half2_rn(b.x, b.y), __floats2half2_rn(b.z, b.w) };
        *(uint2*)(g_xh + idx*8)     = *(uint2*)&h[0];
        *(uint2*)(g_xh + idx*8 + 4) = *(uint2*)&h[2];
    }

    if (idx < NQKV) {
        float v;
        if (idx < 64)       v = bk[idx];
        else if (idx < 128) v = bv[idx-64];
        else                v = bq[idx-128];
        g_ball[idx] = v;
    }
}

// ---------------- kernel 1b: coalesced smem-tile weight transposes ----------------
__global__ void wtrans_kernel(const float* __restrict__ Wk, const float* __restrict__ Wv,
                              const float* __restrict__ Wq, const float* __restrict__ Wp)
{
    __shared__ float t[32][33];
    const int slab = blockIdx.z;
    const int k0 = blockIdx.x * 32, n0 = blockIdx.y * 32;
    const float* src;
    __half* dst;
    if (slab == 0)      src = Wk;
    else if (slab == 1) src = Wv;
    else if (slab < 10) src = Wq + (size_t)(slab-2)*WRD*HD;
    else                src = Wp;
    dst = (slab < 10) ? (g_WhT + (size_t)slab*64*WRD) : g_WpT;

    const int tx = threadIdx.x, ty = threadIdx.y;   // (32, 8)
    #pragma unroll
    for (int r = 0; r < 4; r++)
        t[ty + r*8][tx] = src[(size_t)(k0 + ty + r*8)*HD + n0 + tx];
    __syncthreads();
    #pragma unroll
    for (int r = 0; r < 4; r++) {
        int n = ty + r*8;
        dst[(size_t)(n0 + n)*WRD + k0 + tx] = __float2half_rn(t[tx][n]);
    }
}

// ---------------- kernel 2: QKV projection, cp.async double-buffered ----------------
// grid (64, 10), 256 thr (8 warps x 16 m-rows). Tile 128m x 64n, K-step 64.
__global__ __launch_bounds__(256) void qkv_mma_kernel()
{
    __shared__ __align__(128) char sA[2][128*128];   // 2 x 16KB
    __shared__ __align__(128) char sB[2][64*128];    // 2 x  8KB

    const int tid = threadIdx.x;
    const int wid = tid >> 5, lane = tid & 31;
    const int m0 = blockIdx.x * 128, n0 = blockIdx.y * 64;

    auto load_tiles = [&](int buf, int k0) {
        #pragma unroll
        for (int r = 0; r < 4; r++) {
            int i = tid + r*256;
            int row = i >> 3, c8 = (i & 7) * 8;
            cp16(smem_u32(sA[buf]) + SW128((uint32_t)(row*128 + c8*2)),
                 g_xh + (size_t)(m0 + row)*WRD + k0 + c8);
        }
        #pragma unroll
        for (int r = 0; r < 2; r++) {
            int i = tid + r*256;
            int row = i >> 3, c8 = (i & 7) * 8;
            cp16(smem_u32(sB[buf]) + SW128((uint32_t)(row*128 + c8*2)),
                 g_WhT + (size_t)(n0 + row)*WRD + k0 + c8);
        }
    };

    float acc[8][4] = {};

    load_tiles(0, 0); CP_COMMIT();

    for (int ki = 0; ki < 8; ki++) {
        if (ki < 7) { load_tiles((ki+1)&1, (ki+1)*64); CP_COMMIT(); CP_WAIT(1); }
        else CP_WAIT(0);
        __syncthreads();

        const uint32_t ab = smem_u32(sA[ki&1]), bb = smem_u32(sB[ki&1]);
        #pragma unroll
        for (int kk = 0; kk < 4; kk++) {
            uint32_t afr[4];
            {
                int row = wid*16 + (lane & 7) + ((lane >> 3) & 1) * 8;
                uint32_t col = (uint32_t)(kk*32 + ((lane >> 4) ? 16 : 0));
                ldsm_x4(afr, ab + SW128((uint32_t)row*128 + col));
            }
            uint32_t colb = (uint32_t)(kk*32 + ((lane & 8) ? 16 : 0));
            uint32_t rwb  = (uint32_t)(((lane & 16) ? 8 : 0) + (lane & 7));
            #pragma unroll
            for (int j2 = 0; j2 < 4; j2++) {
                uint32_t bfr[4];
                ldsm_x4(bfr, bb + SW128((j2*16 + rwb)*128 + colb));
                mma16816(acc[2*j2],   afr, bfr);
                mma16816(acc[2*j2+1], afr, bfr + 2);
            }
        }
        __syncthreads();
    }

    // ---- epilogue: bias + scatter to K / V^T / Q ----
    int r = wid*16 + (lane >> 2);
    #pragma unroll
    for (int j = 0; j < 8; j++) {
        #pragma unroll
        for (int e = 0; e < 2; e++) {
            int n = n0 + j*8 + (lane & 3)*2 + e;
            float bias = g_ball[n];
            #pragma unroll
            for (int rr = 0; rr < 2; rr++) {
                int m = m0 + r + rr*8;
                float v = acc[j][rr*2 + e] + bias;
                int b = m >> 12, s = m & 4095;
                if (n < 64) {
                    g_Kh[((size_t)b*SEQ + s)*HD + n] = __float2half_rn(v);
                } else if (n < 128) {
                    g_Vth[((size_t)b*HD + (n-64))*SEQ + s] = __float2half_rn(v);
                } else {
                    int nn = n - 128; int h = nn >> 6, d = nn & 63;
                    g_Qh[(((size_t)b*NH + h)*SEQ + s)*HD + d] = __float2half_rn(v * QSCALE);
                }
            }
        }
    }
}

// ---------------- kernel 3: mma.sync flash attention, fp16-accum S, 3 CTAs/SM ----------------
// grid (SEQ/128, NH, BATCH), 128 threads = 4 warps x 32 q-rows.
// S accumulated in fp16: c-frag == P a-frag layout, exp2 applied in place (no pack phase).
// lsum on the tensor pipe (P @ ones). One __syncthreads per kt.
__global__ __launch_bounds__(128, 3) void attn_mma_kernel()
{
    __shared__ __align__(128) char sQ[128*128];     // 16KB
    __shared__ __align__(128) char sK[2][64*128];   // 2 x 8KB
    __shared__ __align__(128) char sV[2][64*128];   // 2 x 8KB

    const int tid  = threadIdx.x;
    const int wid  = tid >> 5, lane = tid & 31;
    const int b = blockIdx.z, hh = blockIdx.y, q0 = blockIdx.x * 128;

    const __half* Qp = g_Qh + ((size_t)(b*NH + hh)*SEQ + q0) * HD;
    const __half* Kp = g_Kh  + (size_t)b*SEQ*HD;
    const __half* Vp = g_Vth + (size_t)b*HD*SEQ;

    auto load_kv = [&](int buf, int kt) {
        #pragma unroll
        for (int r = 0; r < 4; r++) {
            int i = tid + r*128;
            int row = i >> 3, c8 = (i & 7) * 8;
            uint32_t off = SW128((uint32_t)(row*128 + c8*2));
            cp16(smem_u32(sK[buf]) + off, Kp + (size_t)(kt*64 + row)*HD + c8);
            cp16(smem_u32(sV[buf]) + off, Vp + (size_t)row*SEQ + kt*64 + c8);
        }
    };

    load_kv(0, 0); CP_COMMIT();

    // ---- Q tile -> smem -> register a-frags (2 a-tiles per warp) ----
    const uint32_t qb = smem_u32(sQ);
    #pragma unroll
    for (int r = 0; r < 8; r++) {
        int i = tid + r*128;
        int row = i >> 3, c8 = (i & 7) * 8;
        *(uint4*)(sQ + SW128((uint32_t)(row*128 + c8*2))) = *(const uint4*)(Qp + row*HD + c8);
    }
    __syncthreads();
    uint32_t qa[2][4][4];
    #pragma unroll
    for (int a = 0; a < 2; a++) {
        int row = wid*32 + a*16 + (lane & 7) + ((lane >> 3) & 1) * 8;
        #pragma unroll
        for (int kk = 0; kk < 4; kk++) {
            uint32_t col = (uint32_t)(kk*32 + ((lane >> 4) ? 16 : 0));
            ldsm_x4(qa[a][kk], qb + SW128((uint32_t)row*128 + col));
        }
    }

    float oc[2][8][4] = {};
    float lsacc[2][4] = {};                     // tensor-pipe lsum accumulators (P @ ones)
    const uint32_t ones_frag[2] = { 0x3C003C00u, 0x3C003C00u };  // fp16 1.0 x4
    const uint32_t colb = (uint32_t)((lane & 8) ? 16 : 0);
    const uint32_t rwb  = (uint32_t)(((lane & 16) ? 8 : 0) + (lane & 7));

    for (int kt = 0; kt < SEQ/64; kt++) {
        CP_WAIT(0);
        __syncthreads();   // data for buf kt&1 visible; all warps done reading buf (kt+1)&1
        if (kt < SEQ/64 - 1) { load_kv((kt+1)&1, kt+1); CP_COMMIT(); }

        const uint32_t kb_ = smem_u32(sK[kt&1]), vb_ = smem_u32(sV[kt&1]);

        // ---- S = Q @ K^T, fp16 accumulate (c-frags are future P a-frags) ----
        uint32_t scf[2][8][2] = {};
        #pragma unroll
        for (int kk = 0; kk < 4; kk++) {
            uint32_t cc = (uint32_t)(kk*32) + colb;
            #pragma unroll
            for (int j2 = 0; j2 < 4; j2++) {
                uint32_t bfr[4];
                ldsm_x4(bfr, kb_ + SW128((j2*16 + rwb)*128 + cc));
                #pragma unroll
                for (int a = 0; a < 2; a++) {
                    mma16816_f16(scf[a][2*j2],   qa[a][kk], bfr);
                    mma16816_f16(scf[a][2*j2+1], qa[a][kk], bfr + 2);
                }
            }
        }

        // ---- exp2 in place on the fp16 c-frags: P ready, zero pack work ----
        #pragma unroll
        for (int a = 0; a < 2; a++)
            #pragma unroll
            for (int j = 0; j < 8; j++) {
                __half2 e0 = h2exp2(*(__half2*)&scf[a][j][0]);
                __half2 e1 = h2exp2(*(__half2*)&scf[a][j][1]);
                scf[a][j][0] = *(uint32_t*)&e0;
                scf[a][j][1] = *(uint32_t*)&e1;
            }

        // ---- O += P @ V^T, lsum += P @ ones ----
        #pragma unroll
        for (int tt = 0; tt < 4; tt++) {
            uint32_t cc = (uint32_t)(tt*32) + colb;
            uint32_t pa[2][4];
            #pragma unroll
            for (int a = 0; a < 2; a++) {
                pa[a][0] = scf[a][2*tt][0];
                pa[a][1] = scf[a][2*tt][1];
                pa[a][2] = scf[a][2*tt+1][0];
                pa[a][3] = scf[a][2*tt+1][1];
            }
            #pragma unroll
            for (int jv = 0; jv < 4; jv++) {
                uint32_t bfr[4];
                ldsm_x4(bfr, vb_ + SW128((jv*16 + rwb)*128 + cc));
                #pragma unroll
                for (int a = 0; a < 2; a++) {
                    mma16816(oc[a][2*jv],   pa[a], bfr);
                    mma16816(oc[a][2*jv+1], pa[a], bfr + 2);
                }
            }
            #pragma unroll
            for (int a = 0; a < 2; a++)
                mma16816(lsacc[a], pa[a], ones_frag);
        }
    }

    // ---- write O (fp16 concat-head layout); lsum complete per lane ----
    int c0 = (lane & 3) * 2;
    #pragma unroll
    for (int a = 0; a < 2; a++) {
        float inv0 = 1.0f / lsacc[a][0], inv1 = 1.0f / lsacc[a][2];
        int r = wid*32 + a*16 + (lane >> 2);
        __half* Z0 = g_Zch + ((size_t)(b*SEQ) + q0 + r    )*(NH*HD) + hh*HD;
        __half* Z1 = g_Zch + ((size_t)(b*SEQ) + q0 + r + 8)*(NH*HD) + hh*HD;
        #pragma unroll
        for (int j = 0; j < 8; j++) {
            int d = j*8 + c0;
            *(__half2*)(Z0 + d) = __floats2half2_rn(oc[a][j][0]*inv0, oc[a][j][1]*inv0);
            *(__half2*)(Z1 + d) = __floats2half2_rn(oc[a][j][2]*inv1, oc[a][j][3]*inv1);
        }
    }
}

// ---------------- kernel 4: output projection, cp.async double-buffered ----------------
// grid (128), 128 thr (4 warps x 16 m-rows). Tile 64m x 64n, K-step 64.
__global__ __launch_bounds__(128) void oproj_mma_kernel(const float* __restrict__ bp,
                                                        float* __restrict__ out)
{
    __shared__ __align__(128) char sA[2][64*128];    // 2 x 8KB
    __shared__ __align__(128) char sB[2][64*128];    // 2 x 8KB

    const int tid = threadIdx.x;
    const int wid = tid >> 5, lane = tid & 31;
    const int m0 = blockIdx.x * 64;

    auto load_tiles = [&](int buf, int k0) {
        #pragma unroll
        for (int r = 0; r < 4; r++) {
            int i = tid + r*128;
            int row = i >> 3, c8 = (i & 7) * 8;
            uint32_t off = SW128((uint32_t)(row*128 + c8*2));
            cp16(smem_u32(sA[buf]) + off, g_Zch + (size_t)(m0 + row)*WRD + k0 + c8);
            cp16(smem_u32(sB[buf]) + off, g_WpT + (size_t)row*WRD + k0 + c8);
        }
    };

    float acc[8][4] = {};

    load_tiles(0, 0); CP_COMMIT();

    for (int ki = 0; ki < 8; ki++) {
        if (ki < 7) { load_tiles((ki+1)&1, (ki+1)*64); CP_COMMIT(); CP_WAIT(1); }
        else CP_WAIT(0);
        __syncthreads();

        const uint32_t ab = smem_u32(sA[ki&1]), bb = smem_u32(sB[ki&1]);
        #pragma unroll
        for (int kk = 0; kk < 4; kk++) {
            uint32_t afr[4];
            {
                int row = wid*16 + (lane & 7) + ((lane >> 3) & 1) * 8;
                uint32_t col = (uint32_t)(kk*32 + ((lane >> 4) ? 16 : 0));
                ldsm_x4(afr, ab + SW128((uint32_t)row*128 + col));
            }
            uint32_t colb = (uint32_t)(kk*32 + ((lane & 8) ? 16 : 0));
            uint32_t rwb  = (uint32_t)(((lane & 16) ? 8 : 0) + (lane & 7));
            #pragma unroll
            for (int j2 = 0; j2 < 4; j2++) {
                uint32_t bfr[4];
                ldsm_x4(bfr, bb + SW128((j2*16 + rwb)*128 + colb));
                mma16816(acc[2*j2],   afr, bfr);
                mma16816(acc[2*j2+1], afr, bfr + 2);
            }
        }
        __syncthreads();
    }

    int r  = wid*16 + (lane >> 2);
    int c0 = (lane & 3) * 2;
    float* O0 = out + (size_t)(m0 + r    )*HD;
    float* O1 = out + (size_t)(m0 + r + 8)*HD;
    #pragma unroll
    for (int j = 0; j < 8; j++) {
        int n = j*8 + c0;
        float b0 = bp[n], b1 = bp[n+1];
        *(float2*)(O0 + n) = make_float2(acc[j][0] + b0, acc[j][1] + b1);
        *(float2*)(O1 + n) = make_float2(acc[j][2] + b0, acc[j][3] + b1);
    }
}

// ---------------- launch ----------------
extern "C" void kernel_launch(void* const* d_in, const int* in_sizes, int n_in,
                              void* d_out, int out_size)
{
    const float* x  = (const float*)d_in[0];
    const float* Wq = (const float*)d_in[1];
    const float* bq = (const float*)d_in[2];
    const float* Wk = (const float*)d_in[3];
    const float* bk = (const float*)d_in[4];
    const float* Wv = (const float*)d_in[5];
    const float* bv = (const float*)d_in[6];
    const float* Wp = (const float*)d_in[7];
    const float* bp = (const float*)d_in[8];
    float* out = (float*)d_out;

    prep_kernel<<<(MTOT*WRD/8 + 255)/256, 256>>>(x, bk, bv, bq);
    wtrans_kernel<<<dim3(16, 2, 11), dim3(32, 8)>>>(Wk, Wv, Wq, Wp);

    qkv_mma_kernel<<<dim3(MTOT/128, NQKV/64), 256>>>();

    attn_mma_kernel<<<dim3(SEQ/128, NH, BATCH), 128>>>();

    oproj_mma_kernel<<<dim3(MTOT/64), 128>>>(bp, out);
}

// round 11
// speedup vs baseline: 1.1122x; 1.0318x over previous
#include <cuda_runtime.h>
#include <cuda_fp16.h>
#include <math.h>
#include <cstdint>

#define BATCH 2
#define NH    8
#define SEQ   4096
#define HD    64
#define WRD   512
#define MTOT  (BATCH*SEQ)     // 8192
#define NQKV  640             // 64 (K) + 64 (V) + 8*64 (Q)
#define NKT   (SEQ/64)        // 64 key tiles

// Q pre-scale: (1/sqrt(64)) * log2(e)  -> scores in log2 domain, exp2 for softmax
#define QSCALE 0.18033688011112042f

// ---------------- scratch (device globals; no allocation allowed) ----------------
__device__ __half g_xh[MTOT*WRD];            // x fp16 [8192,512]
__device__ __half g_WhT[NQKV*WRD];           // packed QKV weight, transposed [n][k] fp16
__device__ __half g_WpT[HD*WRD];             // Wp transposed [n][k] fp16
__device__ float  g_ball[NQKV];              // packed QKV bias fp32
__device__ __half g_Kh[BATCH*SEQ*HD];        // K  [b,t,d] fp16
__device__ __half g_Vth[BATCH*HD*SEQ];       // V^T [b,d,t] fp16
__device__ __half g_Qh[BATCH*NH*SEQ*HD];     // Q  [b,h,s,d] fp16 (pre-scaled)
__device__ __half g_Zch[BATCH*SEQ*NH*HD];    // concat heads [b,s,h*d] fp16

#define SW128(off) ((off) ^ (((off) >> 3) & 0x70))

__device__ __forceinline__ uint32_t smem_u32(const void* p) {
    uint32_t a;
    asm("{ .reg .u64 t; cvta.to.shared.u64 t, %1; cvt.u32.u64 %0, t; }" : "=r"(a) : "l"(p));
    return a;
}
__device__ __forceinline__ void mma16816(float c[4], const uint32_t a[4], const uint32_t b[2]) {
    asm volatile("mma.sync.aligned.m16n8k16.row.col.f32.f16.f16.f32 "
        "{%0,%1,%2,%3}, {%4,%5,%6,%7}, {%8,%9}, {%0,%1,%2,%3};"
        : "+f"(c[0]), "+f"(c[1]), "+f"(c[2]), "+f"(c[3])
        : "r"(a[0]), "r"(a[1]), "r"(a[2]), "r"(a[3]), "r"(b[0]), "r"(b[1]));
}
// fp16-accumulated MMA: c-frag (2 regs) doubles as the P a-frag after in-place exp
__device__ __forceinline__ void mma16816_f16(uint32_t c[2], const uint32_t a[4], const uint32_t b[2]) {
    asm volatile("mma.sync.aligned.m16n8k16.row.col.f16.f16.f16.f16 "
        "{%0,%1}, {%2,%3,%4,%5}, {%6,%7}, {%0,%1};"
        : "+r"(c[0]), "+r"(c[1])
        : "r"(a[0]), "r"(a[1]), "r"(a[2]), "r"(a[3]), "r"(b[0]), "r"(b[1]));
}
__device__ __forceinline__ void ldsm_x4(uint32_t d[4], uint32_t addr) {
    asm volatile("ldmatrix.sync.aligned.m8n8.x4.shared.b16 {%0,%1,%2,%3}, [%4];"
        : "=r"(d[0]), "=r"(d[1]), "=r"(d[2]), "=r"(d[3]) : "r"(addr));
}
__device__ __forceinline__ void cp16(uint32_t sdst, const void* gsrc) {
    asm volatile("cp.async.cg.shared.global [%0], [%1], 16;" :: "r"(sdst), "l"(gsrc));
}
#define CP_COMMIT() asm volatile("cp.async.commit_group;" ::: "memory")
#define CP_WAIT(n)  asm volatile("cp.async.wait_group %0;" :: "n"(n) : "memory")

// ---------------- kernel 1a: convert x to fp16 + pack bias ----------------
__global__ void prep_kernel(const float* __restrict__ x,
                            const float* __restrict__ bk,
                            const float* __restrict__ bv,
                            const float* __restrict__ bq)
{
    int idx = blockIdx.x * blockDim.x + threadIdx.x;

    if (idx < MTOT*WRD/8) {
        float4 a = *(const float4*)(x + idx*8);
        float4 b = *(const float4*)(x + idx*8 + 4);
        __half2 h[4] = { __floats2half2_rn(a.x, a.y), __floats2half2_rn(a.z, a.w),
                         __floats2half2_rn(b.x, b.y), __floats2half2_rn(b.z, b.w) };
        *(uint2*)(g_xh + idx*8)     = *(uint2*)&h[0];
        *(uint2*)(g_xh + idx*8 + 4) = *(uint2*)&h[2];
    }

    if (idx < NQKV) {
        float v;
        if (idx < 64)       v = bk[idx];
        else if (idx < 128) v = bv[idx-64];
        else                v = bq[idx-128];
        g_ball[idx] = v;
    }
}

// ---------------- kernel 1b: coalesced smem-tile weight transposes ----------------
__global__ void wtrans_kernel(const float* __restrict__ Wk, const float* __restrict__ Wv,
                              const float* __restrict__ Wq, const float* __restrict__ Wp)
{
    __shared__ float t[32][33];
    const int slab = blockIdx.z;
    const int k0 = blockIdx.x * 32, n0 = blockIdx.y * 32;
    const float* src;
    __half* dst;
    if (slab == 0)      src = Wk;
    else if (slab == 1) src = Wv;
    else if (slab < 10) src = Wq + (size_t)(slab-2)*WRD*HD;
    else                src = Wp;
    dst = (slab < 10) ? (g_WhT + (size_t)slab*64*WRD) : g_WpT;

    const int tx = threadIdx.x, ty = threadIdx.y;   // (32, 8)
    #pragma unroll
    for (int r = 0; r < 4; r++)
        t[ty + r*8][tx] = src[(size_t)(k0 + ty + r*8)*HD + n0 + tx];
    __syncthreads();
    #pragma unroll
    for (int r = 0; r < 4; r++) {
        int n = ty + r*8;
        dst[(size_t)(n0 + n)*WRD + k0 + tx] = __float2half_rn(t[tx][n]);
    }
}

// ---------------- kernel 2: QKV projection, cp.async double-buffered ----------------
// grid (64, 10), 256 thr (8 warps x 16 m-rows). Tile 128m x 64n, K-step 64.
__global__ __launch_bounds__(256) void qkv_mma_kernel()
{
    __shared__ __align__(128) char sA[2][128*128];   // 2 x 16KB
    __shared__ __align__(128) char sB[2][64*128];    // 2 x  8KB

    const int tid = threadIdx.x;
    const int wid = tid >> 5, lane = tid & 31;
    const int m0 = blockIdx.x * 128, n0 = blockIdx.y * 64;

    auto load_tiles = [&](int buf, int k0) {
        #pragma unroll
        for (int r = 0; r < 4; r++) {
            int i = tid + r*256;
            int row = i >> 3, c8 = (i & 7) * 8;
            cp16(smem_u32(sA[buf]) + SW128((uint32_t)(row*128 + c8*2)),
                 g_xh + (size_t)(m0 + row)*WRD + k0 + c8);
        }
        #pragma unroll
        for (int r = 0; r < 2; r++) {
            int i = tid + r*256;
            int row = i >> 3, c8 = (i & 7) * 8;
            cp16(smem_u32(sB[buf]) + SW128((uint32_t)(row*128 + c8*2)),
                 g_WhT + (size_t)(n0 + row)*WRD + k0 + c8);
        }
    };

    float acc[8][4] = {};

    load_tiles(0, 0); CP_COMMIT();

    for (int ki = 0; ki < 8; ki++) {
        if (ki < 7) { load_tiles((ki+1)&1, (ki+1)*64); CP_COMMIT(); CP_WAIT(1); }
        else CP_WAIT(0);
        __syncthreads();

        const uint32_t ab = smem_u32(sA[ki&1]), bb = smem_u32(sB[ki&1]);
        #pragma unroll
        for (int kk = 0; kk < 4; kk++) {
            uint32_t afr[4];
            {
                int row = wid*16 + (lane & 7) + ((lane >> 3) & 1) * 8;
                uint32_t col = (uint32_t)(kk*32 + ((lane >> 4) ? 16 : 0));
                ldsm_x4(afr, ab + SW128((uint32_t)row*128 + col));
            }
            uint32_t colb = (uint32_t)(kk*32 + ((lane & 8) ? 16 : 0));
            uint32_t rwb  = (uint32_t)(((lane & 16) ? 8 : 0) + (lane & 7));
            #pragma unroll
            for (int j2 = 0; j2 < 4; j2++) {
                uint32_t bfr[4];
                ldsm_x4(bfr, bb + SW128((j2*16 + rwb)*128 + colb));
                mma16816(acc[2*j2],   afr, bfr);
                mma16816(acc[2*j2+1], afr, bfr + 2);
            }
        }
        __syncthreads();
    }

    // ---- epilogue: bias + scatter to K / V^T / Q ----
    int r = wid*16 + (lane >> 2);
    #pragma unroll
    for (int j = 0; j < 8; j++) {
        #pragma unroll
        for (int e = 0; e < 2; e++) {
            int n = n0 + j*8 + (lane & 3)*2 + e;
            float bias = g_ball[n];
            #pragma unroll
            for (int rr = 0; rr < 2; rr++) {
                int m = m0 + r + rr*8;
                float v = acc[j][rr*2 + e] + bias;
                int b = m >> 12, s = m & 4095;
                if (n < 64) {
                    g_Kh[((size_t)b*SEQ + s)*HD + n] = __float2half_rn(v);
                } else if (n < 128) {
                    g_Vth[((size_t)b*HD + (n-64))*SEQ + s] = __float2half_rn(v);
                } else {
                    int nn = n - 128; int h = nn >> 6, d = nn & 63;
                    g_Qh[(((size_t)b*NH + h)*SEQ + s)*HD + d] = __float2half_rn(v * QSCALE);
                }
            }
        }
    }
}

// ---------------- kernel 3: mma.sync flash attention, cross-iteration pipelined ----------------
// grid (SEQ/128, NH, BATCH), 128 threads = 4 warps x 32 q-rows, 2 CTAs/SM.
// 3-deep K/V smem ring (Q staging overlays ring slot 2). Per step kt:
// S(kt+1) + exp(kt+1) interleave with PV(kt) in one basic block — the tensor pipe
// never drains during the exp phase. fp16-accum S (c-frag == P a-frag), lsum = P @ ones.
__global__ __launch_bounds__(128, 2) void attn_mma_kernel()
{
    __shared__ __align__(128) char smemAll[3*16384];   // 48KB: 3 x (K 8KB | V 8KB); slot2 = Q staging in prologue

    const int tid  = threadIdx.x;
    const int wid  = tid >> 5, lane = tid & 31;
    const int b = blockIdx.z, hh = blockIdx.y, q0 = blockIdx.x * 128;

    const __half* Qp = g_Qh + ((size_t)(b*NH + hh)*SEQ + q0) * HD;
    const __half* Kp = g_Kh  + (size_t)b*SEQ*HD;
    const __half* Vp = g_Vth + (size_t)b*HD*SEQ;

    auto kbuf = [&](int r) -> char* { return smemAll + r*16384; };
    auto vbuf = [&](int r) -> char* { return smemAll + r*16384 + 8192; };
    char* sQ = smemAll + 2*16384;

    auto load_kv = [&](int bufr, int kt) {
        char* kb = kbuf(bufr); char* vb = vbuf(bufr);
        #pragma unroll
        for (int r = 0; r < 4; r++) {
            int i = tid + r*128;
            int row = i >> 3, c8 = (i & 7) * 8;
            uint32_t off = SW128((uint32_t)(row*128 + c8*2));
            cp16(smem_u32(kb) + off, Kp + (size_t)(kt*64 + row)*HD + c8);
            cp16(smem_u32(vb) + off, Vp + (size_t)row*SEQ + kt*64 + c8);
        }
    };

    load_kv(0, 0); CP_COMMIT();
    load_kv(1, 1); CP_COMMIT();

    // ---- Q tile -> smem slot2 -> register a-frags ----
    #pragma unroll
    for (int r = 0; r < 8; r++) {
        int i = tid + r*128;
        int row = i >> 3, c8 = (i & 7) * 8;
        *(uint4*)(sQ + SW128((uint32_t)(row*128 + c8*2))) = *(const uint4*)(Qp + row*HD + c8);
    }
    __syncthreads();
    uint32_t qa[2][4][4];
    {
        const uint32_t qb = smem_u32(sQ);
        #pragma unroll
        for (int a = 0; a < 2; a++) {
            int row = wid*32 + a*16 + (lane & 7) + ((lane >> 3) & 1) * 8;
            #pragma unroll
            for (int kk = 0; kk < 4; kk++) {
                uint32_t col = (uint32_t)(kk*32 + ((lane >> 4) ? 16 : 0));
                ldsm_x4(qa[a][kk], qb + SW128((uint32_t)row*128 + col));
            }
        }
    }

    float oc[2][8][4] = {};
    float lsacc[2][4] = {};
    const uint32_t ones_frag[2] = { 0x3C003C00u, 0x3C003C00u };  // fp16 1.0 x4
    const uint32_t colb = (uint32_t)((lane & 8) ? 16 : 0);
    const uint32_t rwb  = (uint32_t)(((lane & 16) ? 8 : 0) + (lane & 7));

    uint32_t scfA[2][8][2], scfB[2][8][2];

#define S_COMPUTE(SCF, KBASE) do { \
    const uint32_t _kb = (KBASE); \
    _Pragma("unroll") for (int a = 0; a < 2; a++) \
      _Pragma("unroll") for (int j = 0; j < 8; j++) { SCF[a][j][0] = 0u; SCF[a][j][1] = 0u; } \
    _Pragma("unroll") for (int kk = 0; kk < 4; kk++) { \
        uint32_t cc = (uint32_t)(kk*32) + colb; \
        _Pragma("unroll") for (int j2 = 0; j2 < 4; j2++) { \
            uint32_t bfr[4]; \
            ldsm_x4(bfr, _kb + SW128((j2*16 + rwb)*128 + cc)); \
            _Pragma("unroll") for (int a = 0; a < 2; a++) { \
                mma16816_f16(SCF[a][2*j2],   qa[a][kk], bfr); \
                mma16816_f16(SCF[a][2*j2+1], qa[a][kk], bfr + 2); \
            } } } } while (0)

#define EXPP(SCF) do { \
    _Pragma("unroll") for (int a = 0; a < 2; a++) \
      _Pragma("unroll") for (int j = 0; j < 8; j++) { \
        __half2 e0 = h2exp2(*(__half2*)&SCF[a][j][0]); \
        __half2 e1 = h2exp2(*(__half2*)&SCF[a][j][1]); \
        SCF[a][j][0] = *(uint32_t*)&e0; SCF[a][j][1] = *(uint32_t*)&e1; } } while (0)

#define PV_COMPUTE(SCF, VBASE) do { \
    const uint32_t _vb = (VBASE); \
    _Pragma("unroll") for (int tt = 0; tt < 4; tt++) { \
        uint32_t cc = (uint32_t)(tt*32) + colb; \
        uint32_t pa[2][4]; \
        _Pragma("unroll") for (int a = 0; a < 2; a++) { \
            pa[a][0] = SCF[a][2*tt][0];   pa[a][1] = SCF[a][2*tt][1]; \
            pa[a][2] = SCF[a][2*tt+1][0]; pa[a][3] = SCF[a][2*tt+1][1]; } \
        _Pragma("unroll") for (int jv = 0; jv < 4; jv++) { \
            uint32_t bfr[4]; \
            ldsm_x4(bfr, _vb + SW128((jv*16 + rwb)*128 + cc)); \
            _Pragma("unroll") for (int a = 0; a < 2; a++) { \
                mma16816(oc[a][2*jv],   pa[a], bfr); \
                mma16816(oc[a][2*jv+1], pa[a], bfr + 2); } } \
        _Pragma("unroll") for (int a = 0; a < 2; a++) \
            mma16816(lsacc[a], pa[a], ones_frag); } } while (0)

#define STEP(CUR, NXT, KT, HASNEXT) do { \
    CP_WAIT(0); \
    __syncthreads(); \
    if ((HASNEXT) && (KT) + 2 < NKT) { load_kv(((KT)+2)%3, (KT)+2); CP_COMMIT(); } \
    if (HASNEXT) { S_COMPUTE(NXT, smem_u32(kbuf(((KT)+1)%3))); } \
    PV_COMPUTE(CUR, smem_u32(vbuf((KT)%3))); \
    if (HASNEXT) { EXPP(NXT); } \
} while (0)

    // ---- prologue: S(0) + exp(0) into scfA (K in slot0) ----
    CP_WAIT(1);
    __syncthreads();
    S_COMPUTE(scfA, smem_u32(kbuf(0)));
    EXPP(scfA);

    // ---- pipelined mainloop ----
    for (int kt = 0; kt < NKT - 2; kt += 2) {
        STEP(scfA, scfB, kt,   true);
        STEP(scfB, scfA, kt+1, true);
    }
    STEP(scfA, scfB, NKT-2, true);
    STEP(scfB, scfA, NKT-1, false);

    // ---- write O (fp16 concat-head layout); lsum complete per lane ----
    int c0 = (lane & 3) * 2;
    #pragma unroll
    for (int a = 0; a < 2; a++) {
        float inv0 = 1.0f / lsacc[a][0], inv1 = 1.0f / lsacc[a][2];
        int r = wid*32 + a*16 + (lane >> 2);
        __half* Z0 = g_Zch + ((size_t)(b*SEQ) + q0 + r    )*(NH*HD) + hh*HD;
        __half* Z1 = g_Zch + ((size_t)(b*SEQ) + q0 + r + 8)*(NH*HD) + hh*HD;
        #pragma unroll
        for (int j = 0; j < 8; j++) {
            int d = j*8 + c0;
            *(__half2*)(Z0 + d) = __floats2half2_rn(oc[a][j][0]*inv0, oc[a][j][1]*inv0);
            *(__half2*)(Z1 + d) = __floats2half2_rn(oc[a][j][2]*inv1, oc[a][j][3]*inv1);
        }
    }
}

// ---------------- kernel 4: output projection, cp.async double-buffered ----------------
// grid (128), 128 thr (4 warps x 16 m-rows). Tile 64m x 64n, K-step 64.
__global__ __launch_bounds__(128) void oproj_mma_kernel(const float* __restrict__ bp,
                                                        float* __restrict__ out)
{
    __shared__ __align__(128) char sA[2][64*128];    // 2 x 8KB
    __shared__ __align__(128) char sB[2][64*128];    // 2 x 8KB

    const int tid = threadIdx.x;
    const int wid = tid >> 5, lane = tid & 31;
    const int m0 = blockIdx.x * 64;

    auto load_tiles = [&](int buf, int k0) {
        #pragma unroll
        for (int r = 0; r < 4; r++) {
            int i = tid + r*128;
            int row = i >> 3, c8 = (i & 7) * 8;
            uint32_t off = SW128((uint32_t)(row*128 + c8*2));
            cp16(smem_u32(sA[buf]) + off, g_Zch + (size_t)(m0 + row)*WRD + k0 + c8);
            cp16(smem_u32(sB[buf]) + off, g_WpT + (size_t)row*WRD + k0 + c8);
        }
    };

    float acc[8][4] = {};

    load_tiles(0, 0); CP_COMMIT();

    for (int ki = 0; ki < 8; ki++) {
        if (ki < 7) { load_tiles((ki+1)&1, (ki+1)*64); CP_COMMIT(); CP_WAIT(1); }
        else CP_WAIT(0);
        __syncthreads();

        const uint32_t ab = smem_u32(sA[ki&1]), bb = smem_u32(sB[ki&1]);
        #pragma unroll
        for (int kk = 0; kk < 4; kk++) {
            uint32_t afr[4];
            {
                int row = wid*16 + (lane & 7) + ((lane >> 3) & 1) * 8;
                uint32_t col = (uint32_t)(kk*32 + ((lane >> 4) ? 16 : 0));
                ldsm_x4(afr, ab + SW128((uint32_t)row*128 + col));
            }
            uint32_t colb = (uint32_t)(kk*32 + ((lane & 8) ? 16 : 0));
            uint32_t rwb  = (uint32_t)(((lane & 16) ? 8 : 0) + (lane & 7));
            #pragma unroll
            for (int j2 = 0; j2 < 4; j2++) {
                uint32_t bfr[4];
                ldsm_x4(bfr, bb + SW128((j2*16 + rwb)*128 + colb));
                mma16816(acc[2*j2],   afr, bfr);
                mma16816(acc[2*j2+1], afr, bfr + 2);
            }
        }
        __syncthreads();
    }

    int r  = wid*16 + (lane >> 2);
    int c0 = (lane & 3) * 2;
    float* O0 = out + (size_t)(m0 + r    )*HD;
    float* O1 = out + (size_t)(m0 + r + 8)*HD;
    #pragma unroll
    for (int j = 0; j < 8; j++) {
        int n = j*8 + c0;
        float b0 = bp[n], b1 = bp[n+1];
        *(float2*)(O0 + n) = make_float2(acc[j][0] + b0, acc[j][1] + b1);
        *(float2*)(O1 + n) = make_float2(acc[j][2] + b0, acc[j][3] + b1);
    }
}

// ---------------- launch ----------------
extern "C" void kernel_launch(void* const* d_in, const int* in_sizes, int n_in,
                              void* d_out, int out_size)
{
    const float* x  = (const float*)d_in[0];
    const float* Wq = (const float*)d_in[1];
    const float* bq = (const float*)d_in[2];
    const float* Wk = (const float*)d_in[3];
    const float* bk = (const float*)d_in[4];
    const float* Wv = (const float*)d_in[5];
    const float* bv = (const float*)d_in[6];
    const float* Wp = (const float*)d_in[7];
    const float* bp = (const float*)d_in[8];
    float* out = (float*)d_out;

    prep_kernel<<<(MTOT*WRD/8 + 255)/256, 256>>>(x, bk, bv, bq);
    wtrans_kernel<<<dim3(16, 2, 11), dim3(32, 8)>>>(Wk, Wv, Wq, Wp);

    qkv_mma_kernel<<<dim3(MTOT/128, NQKV/64), 256>>>();

    attn_mma_kernel<<<dim3(SEQ/128, NH, BATCH), 128>>>();

    oproj_mma_kernel<<<dim3(MTOT/64), 128>>>(bp, out);
}